// round 7
// baseline (speedup 1.0000x reference)
#include <cuda_runtime.h>
#include <cstdint>

#define C 512
#define NBINS 256
#define RPB 8
#define LIST_CAP 512   // = C: boundary bins can never overflow

// k thresholds for C=512: int(C/2), int(C*2/3), int(C*3/4), int(C*4/5)
#define K1 256u
#define K2 341u
#define K3 384u
#define K4 409u

// Monotone 32-bit key: larger float -> larger key.
__device__ __forceinline__ unsigned int mono_key(float x)
{
    unsigned int u = __float_as_uint(x);
    return u ^ (((unsigned int)((int)u >> 31)) | 0x80000000u);
}

// Descending-value bin (bin 0 = largest values), monotone non-increasing in x.
__device__ __forceinline__ int bin_of(float x)
{
    int b = __float2int_rd(fmaf(x, -32.0f, 128.0f));
    return max(0, min(255, b));
}

// zero-byte detector: 0x80 set in each byte of t that is zero
#define ZB(t) ((((t) - 0x01010101u) & ~(t)) & 0x80808080u)

__global__ __launch_bounds__(32 * RPB, 4)
void multiscale_topk_kernel(const float* __restrict__ attn,
                            const float* __restrict__ w1p,
                            const float* __restrict__ w2p,
                            const float* __restrict__ w3p,
                            const float* __restrict__ w4p,
                            float* __restrict__ out)
{
    __shared__ unsigned int       cnt[RPB][NBINS];
    __shared__ float              se [RPB][NBINS];   // per-bin exp sums; reused as coef LUT
    __shared__ unsigned long long list[RPB][LIST_CAP];
    __shared__ unsigned int       listN[RPB];
    __shared__ uint4              bbs[RPB];          // per k: (bflip<<16) | g
    __shared__ float4             Ss [RPB];          // per k: exp-sum of strictly-better bins
    __shared__ unsigned long long Tk[RPB][4];        // full 64-bit threshold keys

    const int lane = threadIdx.x & 31;
    const int wrow = threadIdx.x >> 5;
    const int row  = blockIdx.x * RPB + wrow;
    const float* __restrict__ rp = attn + (size_t)row * C;

    // ---- init ----
    {
        uint4 z = make_uint4(0u, 0u, 0u, 0u);
        *(uint4*)&cnt[wrow][lane * 8]     = z;
        *(uint4*)&cnt[wrow][lane * 8 + 4] = z;
        *(uint4*)&se [wrow][lane * 8]     = *(uint4*)&z;
        *(uint4*)&se [wrow][lane * 8 + 4] = *(uint4*)&z;
        if (lane == 0) listN[wrow] = 0u;
    }
    const float w1 = __ldg(w1p), w2 = __ldg(w2p), w3 = __ldg(w3p), w4 = __ldg(w4p);

    // ---- load 16 elems / lane (coalesced float4) ----
    float4 X[4];
    #pragma unroll
    for (int g = 0; g < 4; g++)
        X[g] = ((const float4*)rp)[lane + 32 * g];

    __syncwarp();

    // ---- pass A: bins, exp, count + exp-sum histograms; X := exp(x) ----
    unsigned int binw[4];
    {
        float* xv = (float*)X;
        #pragma unroll
        for (int g = 0; g < 4; g++) {
            unsigned int bw = 0u;
            #pragma unroll
            for (int e = 0; e < 4; e++) {
                int i = 4 * g + e;
                float x = xv[i];
                int b = bin_of(x);
                bw |= (unsigned int)b << (8 * e);
                float ee = __expf(x);           // softmax shift-invariant; |x| ~ 5
                atomicAdd(&cnt[wrow][b], 1u);
                atomicAdd(&se[wrow][b], ee);
                xv[i] = ee;
            }
            binw[g] = bw;
        }
    }
    __syncwarp();

    // ---- scan: counts + float prefix; locate boundary bins; capture S_k ----
    {
        uint4  c0 = *(uint4*)&cnt[wrow][lane * 8];
        uint4  c1 = *(uint4*)&cnt[wrow][lane * 8 + 4];
        float4 f0 = *(float4*)&se[wrow][lane * 8];
        float4 f1 = *(float4*)&se[wrow][lane * 8 + 4];
        unsigned int cc[8] = {c0.x, c0.y, c0.z, c0.w, c1.x, c1.y, c1.z, c1.w};
        float        ff[8] = {f0.x, f0.y, f0.z, f0.w, f1.x, f1.y, f1.z, f1.w};
        unsigned int tot = 0u; float totf = 0.f;
        #pragma unroll
        for (int j = 0; j < 8; j++) { tot += cc[j]; totf += ff[j]; }
        unsigned int ti = tot; float tf = totf;
        #pragma unroll
        for (int d = 1; d < 32; d <<= 1) {
            unsigned int v  = __shfl_up_sync(0xffffffffu, ti, d);
            float        vf = __shfl_up_sync(0xffffffffu, tf, d);
            if (lane >= d) { ti += v; tf += vf; }
        }
        unsigned int run  = ti - tot;   // exclusive count prefix
        float        runf = tf - totf;  // exclusive float prefix
        #pragma unroll
        for (int j = 0; j < 8; j++) {
            unsigned int G = run, E = run + cc[j];
            if (G < K4 && E >= K1) {
                unsigned int b = (unsigned int)(lane * 8 + j);
                unsigned int w = ((b ^ 255u) << 16) | G;
                if (G < K1 && E >= K1) { bbs[wrow].x = w; Ss[wrow].x = runf; }
                if (G < K2 && E >= K2) { bbs[wrow].y = w; Ss[wrow].y = runf; }
                if (G < K3 && E >= K3) { bbs[wrow].z = w; Ss[wrow].z = runf; }
                if (G < K4 && E >= K4) { bbs[wrow].w = w; Ss[wrow].w = runf; }
            }
            run = E; runf += ff[j];
        }
    }
    __syncwarp();

    const uint4  B = bbs[wrow];
    const float4 S = Ss[wrow];
    const unsigned int fv1 = B.x >> 16, fv2 = B.y >> 16, fv3 = B.z >> 16, fv4 = B.w >> 16;
    const unsigned int gg1 = B.x & 0xFFFFu, gg2 = B.y & 0xFFFFu,
                       gg3 = B.z & 0xFFFFu, gg4 = B.w & 0xFFFFu;

    // ---- vectorized amb detection (bin == some boundary bin) ----
    unsigned int ambm = 0u;
    {
        const unsigned int k1x4 = (fv1 ^ 255u) * 0x01010101u;
        const unsigned int k2x4 = (fv2 ^ 255u) * 0x01010101u;
        const unsigned int k3x4 = (fv3 ^ 255u) * 0x01010101u;
        const unsigned int k4x4 = (fv4 ^ 255u) * 0x01010101u;
        #pragma unroll
        for (int g = 0; g < 4; g++) {
            unsigned int w = binw[g];
            unsigned int z = ZB(w ^ k1x4) | ZB(w ^ k2x4) | ZB(w ^ k3x4) | ZB(w ^ k4x4);
            ambm |= ((((z >> 7) * 0x01020408u) >> 24) & 0xFu) << (4 * g);
        }
    }

    // ---- gather boundary candidates (reload x; ~2/lane) ----
    {
        unsigned int am = ambm;
        while (am) {
            int i = __ffs(am) - 1; am &= am - 1;
            int gidx = 4 * lane + 128 * (i >> 2) + (i & 3);
            float x = __ldg(rp + gidx);
            unsigned int b = (binw[i >> 2] >> (8 * (i & 3))) & 255u;
            unsigned long long key = ((unsigned long long)(b ^ 255u) << 48)
                | ((unsigned long long)mono_key(x) << 16)
                | (unsigned long long)(65535u - (unsigned int)gidx);
            unsigned int pos = atomicAdd(&listN[wrow], 1u);
            list[wrow][pos] = key;
        }
    }
    __syncwarp();

    // ---- selection: exact k-th largest keys ----
    const unsigned int M = listN[wrow];
    for (unsigned int j = lane; j < M; j += 32) {
        unsigned long long cj = list[wrow][j];
        unsigned int hb = (unsigned int)(cj >> 48);
        unsigned int g0 = (hb == fv1) ? gg1 : (hb == fv2) ? gg2
                        : (hb == fv3) ? gg3 : gg4;
        unsigned int r = g0;
        for (unsigned int q = 0u; q < M; q++) {
            unsigned long long cq = list[wrow][q];
            r += (unsigned int)((cq > cj) && ((unsigned int)(cq >> 48) == hb));
        }
        if (hb == fv1 && r == K1 - 1u) Tk[wrow][0] = cj;
        if (hb == fv2 && r == K2 - 1u) Tk[wrow][1] = cj;
        if (hb == fv3 && r == K3 - 1u) Tk[wrow][2] = cj;
        if (hb == fv4 && r == K4 - 1u) Tk[wrow][3] = cj;
    }
    __syncwarp();

    const unsigned long long T1 = Tk[wrow][0], T2 = Tk[wrow][1],
                             T3 = Tk[wrow][2], T4 = Tk[wrow][3];

    // ---- finalize s_k = S_k + boundary-bin partial ----
    float a1 = 0.f, a2 = 0.f, a3 = 0.f, a4 = 0.f;
    for (unsigned int j = lane; j < M; j += 32) {
        unsigned long long cj = list[wrow][j];
        unsigned int hb = (unsigned int)(cj >> 48);
        unsigned int mk = (unsigned int)(cj >> 16);
        float x = __uint_as_float((mk & 0x80000000u) ? (mk & 0x7FFFFFFFu) : ~mk);
        float e = __expf(x);
        if (hb == fv1 && cj >= T1) a1 += e;
        if (hb == fv2 && cj >= T2) a2 += e;
        if (hb == fv3 && cj >= T3) a3 += e;
        if (hb == fv4 && cj >= T4) a4 += e;
    }
    #pragma unroll
    for (int o = 16; o > 0; o >>= 1) {
        a1 += __shfl_xor_sync(0xffffffffu, a1, o);
        a2 += __shfl_xor_sync(0xffffffffu, a2, o);
        a3 += __shfl_xor_sync(0xffffffffu, a3, o);
        a4 += __shfl_xor_sync(0xffffffffu, a4, o);
    }
    const float q1 = __fdividef(w1, S.x + a1), q2 = __fdividef(w2, S.y + a2),
                q3 = __fdividef(w3, S.z + a3), q4 = __fdividef(w4, S.w + a4);

    // ---- build coef LUT over bins (reuse se); boundary bins overridden later ----
    __syncwarp();
    #pragma unroll
    for (int j = 0; j < 8; j++) {
        unsigned int b = (unsigned int)(lane * 8 + j), bf = b ^ 255u;
        float cf = 0.f;
        if (bf > fv1) cf += q1;
        if (bf > fv2) cf += q2;
        if (bf > fv3) cf += q3;
        if (bf > fv4) cf += q4;
        se[wrow][b] = cf;
    }
    __syncwarp();

    // ---- write: coef = LUT[bin]; exact key compare for boundary elems ----
    {
        const float* ev = (const float*)X;
        float4* op = (float4*)(out + (size_t)row * C);
        #pragma unroll
        for (int g = 0; g < 4; g++) {
            float4 o4;
            float* o = (float*)&o4;
            #pragma unroll
            for (int e = 0; e < 4; e++) {
                int i = 4 * g + e;
                unsigned int b = (binw[g] >> (8 * e)) & 255u;
                float cf = se[wrow][b];
                if ((ambm >> i) & 1u) {
                    int gidx = 4 * lane + 128 * g + e;
                    float x = __ldg(rp + gidx);
                    unsigned long long key = ((unsigned long long)(b ^ 255u) << 48)
                        | ((unsigned long long)mono_key(x) << 16)
                        | (unsigned long long)(65535u - (unsigned int)gidx);
                    cf = 0.f;
                    if (key >= T1) cf += q1;
                    if (key >= T2) cf += q2;
                    if (key >= T3) cf += q3;
                    if (key >= T4) cf += q4;
                }
                o[e] = ev[i] * cf;
            }
            op[lane + 32 * g] = o4;
        }
    }
}

extern "C" void kernel_launch(void* const* d_in, const int* in_sizes, int n_in,
                              void* d_out, int out_size)
{
    const float* attn = (const float*)d_in[0];
    const float* w1   = (const float*)d_in[1];
    const float* w2   = (const float*)d_in[2];
    const float* w3   = (const float*)d_in[3];
    const float* w4   = (const float*)d_in[4];
    float* out = (float*)d_out;

    int rows   = in_sizes[0] / C;
    int blocks = rows / RPB;
    multiscale_topk_kernel<<<blocks, 32 * RPB>>>(attn, w1, w2, w3, w4, out);
}

// round 8
// speedup vs baseline: 1.2231x; 1.2231x over previous
#include <cuda_runtime.h>
#include <cstdint>

#define C 512
#define NBINS 256
#define RPB 8
#define LIST_CAP 512   // = C: boundary bins can never overflow

// k thresholds for C=512: int(C/2), int(C*2/3), int(C*3/4), int(C*4/5)
#define K1 256u
#define K2 341u
#define K3 384u
#define K4 409u

// Fixed-exponent quantization: y = x + 3*2^17 has ulp = 1/32 over |x|<4.
#define OFFF 393216.0f
#define TOPB 0x48C00080u   // bits(393220.0f) = bits(OFFF + 4.0)

// Monotone 32-bit key: larger float -> larger key. (Boundary elems only.)
__device__ __forceinline__ unsigned int mono_key(float x)
{
    unsigned int u = __float_as_uint(x);
    return u ^ (((unsigned int)((int)u >> 31)) | 0x80000000u);
}

// zero-byte detector: 0x80 set in each byte of t that is zero
#define ZB(t) ((((t) - 0x01010101u) & ~(t)) & 0x80808080u)

__global__ __launch_bounds__(32 * RPB, 4)
void multiscale_topk_kernel(const float* __restrict__ attn,
                            const float* __restrict__ w1p,
                            const float* __restrict__ w2p,
                            const float* __restrict__ w3p,
                            const float* __restrict__ w4p,
                            float* __restrict__ out)
{
    __shared__ unsigned int       cnt[RPB][NBINS];
    __shared__ float              lut[RPB][NBINS];   // coef per bin (built late)
    __shared__ unsigned long long list[RPB][LIST_CAP];
    __shared__ unsigned int       listN[RPB];
    __shared__ uint4              bbs[RPB];          // per k: (bin<<16) | G
    __shared__ unsigned long long Tk[RPB][4];        // full 64-bit threshold keys

    const int lane = threadIdx.x & 31;
    const int wrow = threadIdx.x >> 5;
    const int row  = blockIdx.x * RPB + wrow;
    const float* __restrict__ rp = attn + (size_t)row * C;

    // ---- init ----
    {
        uint4 z = make_uint4(0u, 0u, 0u, 0u);
        *(uint4*)&cnt[wrow][lane * 8]     = z;
        *(uint4*)&cnt[wrow][lane * 8 + 4] = z;
        if (lane == 0) listN[wrow] = 0u;
    }
    const float w1 = __ldg(w1p), w2 = __ldg(w2p), w3 = __ldg(w3p), w4 = __ldg(w4p);

    // ---- load 16 elems / lane (coalesced float4) ----
    float4 X[4];
    #pragma unroll
    for (int g = 0; g < 4; g++)
        X[g] = ((const float4*)rp)[lane + 32 * g];

    __syncwarp();

    // ---- pass A: exact-bit bins + count histogram (x kept in X) ----
    unsigned int binw[4];
    {
        const float* xv = (const float*)X;
        #pragma unroll
        for (int g = 0; g < 4; g++) {
            unsigned int bw = 0u;
            #pragma unroll
            for (int e = 0; e < 4; e++) {
                float y = xv[4 * g + e] + OFFF;
                int raw = (int)TOPB - (int)__float_as_uint(y);
                int b = max(0, min(255, raw));
                bw |= (unsigned int)b << (8 * e);
                atomicAdd(&cnt[wrow][b], 1u);
            }
            binw[g] = bw;
        }
    }
    __syncwarp();

    // ---- scan 256 bins; locate the 4 boundary bins (G < k <= G+cnt) ----
    {
        uint4 c0 = *(uint4*)&cnt[wrow][lane * 8];
        uint4 c1 = *(uint4*)&cnt[wrow][lane * 8 + 4];
        unsigned int cc[8] = {c0.x, c0.y, c0.z, c0.w, c1.x, c1.y, c1.z, c1.w};
        unsigned int tot = 0u;
        #pragma unroll
        for (int j = 0; j < 8; j++) tot += cc[j];
        unsigned int ti = tot;
        #pragma unroll
        for (int d = 1; d < 32; d <<= 1) {
            unsigned int v = __shfl_up_sync(0xffffffffu, ti, d);
            if (lane >= d) ti += v;
        }
        unsigned int run = ti - tot;               // exclusive prefix
        #pragma unroll
        for (int j = 0; j < 8; j++) {
            unsigned int G = run, E = run + cc[j];
            if (G < K4 && E >= K1) {
                unsigned int w = ((unsigned int)(lane * 8 + j) << 16) | G;
                if (G < K1 && E >= K1) bbs[wrow].x = w;
                if (G < K2 && E >= K2) bbs[wrow].y = w;
                if (G < K3 && E >= K3) bbs[wrow].z = w;
                if (G < K4 && E >= K4) bbs[wrow].w = w;
            }
            run = E;
        }
    }
    __syncwarp();

    const uint4 B = bbs[wrow];
    const unsigned int bk1 = B.x >> 16, bk2 = B.y >> 16, bk3 = B.z >> 16, bk4 = B.w >> 16;
    const unsigned int gg1 = B.x & 0xFFFFu, gg2 = B.y & 0xFFFFu,
                       gg3 = B.z & 0xFFFFu, gg4 = B.w & 0xFFFFu;
    // Exact fast-path edges: bin < b_k  <=>  y > E_k  (both positive floats)
    const float E1 = __uint_as_float(TOPB - bk1);
    const float E2 = __uint_as_float(TOPB - bk2);
    const float E3 = __uint_as_float(TOPB - bk3);
    const float E4 = __uint_as_float(TOPB - bk4);

    // ---- vectorized amb detection (bin byte == some boundary bin) ----
    unsigned int ambm = 0u;
    {
        const unsigned int k1x4 = bk1 * 0x01010101u;
        const unsigned int k2x4 = bk2 * 0x01010101u;
        const unsigned int k3x4 = bk3 * 0x01010101u;
        const unsigned int k4x4 = bk4 * 0x01010101u;
        #pragma unroll
        for (int g = 0; g < 4; g++) {
            unsigned int w = binw[g];
            unsigned int z = ZB(w ^ k1x4) | ZB(w ^ k2x4) | ZB(w ^ k3x4) | ZB(w ^ k4x4);
            ambm |= ((((z >> 7) * 0x01020408u) >> 24) & 0xFu) << (4 * g);
        }
    }

    // ---- gather boundary candidates (x still live in X) ----
    {
        const float* xv = (const float*)X;
        unsigned int am = ambm;
        while (am) {
            int i = __ffs(am) - 1; am &= am - 1;
            int gidx = 4 * lane + 128 * (i >> 2) + (i & 3);
            unsigned int b = (binw[i >> 2] >> (8 * (i & 3))) & 255u;
            unsigned long long key = ((unsigned long long)b << 48)
                | ((unsigned long long)mono_key(xv[i]) << 16)
                | (unsigned long long)(65535u - (unsigned int)gidx);
            unsigned int pos = atomicAdd(&listN[wrow], 1u);
            list[wrow][pos] = key;
        }
    }
    __syncwarp();

    // ---- selection: exact k-th largest key per boundary bin ----
    {
        const unsigned int M = listN[wrow];
        for (unsigned int j = lane; j < M; j += 32) {
            unsigned long long cj = list[wrow][j];
            unsigned int hb = (unsigned int)(cj >> 48);
            unsigned int g0 = (hb == bk1) ? gg1 : (hb == bk2) ? gg2
                            : (hb == bk3) ? gg3 : gg4;
            unsigned int r = g0;
            for (unsigned int q = 0u; q < M; q++) {
                unsigned long long cq = list[wrow][q];
                r += (unsigned int)((cq > cj) && ((unsigned int)(cq >> 48) == hb));
            }
            if (hb == bk1 && r == K1 - 1u) Tk[wrow][0] = cj;
            if (hb == bk2 && r == K2 - 1u) Tk[wrow][1] = cj;
            if (hb == bk3 && r == K3 - 1u) Tk[wrow][2] = cj;
            if (hb == bk4 && r == K4 - 1u) Tk[wrow][3] = cj;
        }
    }
    __syncwarp();

    // ---- corrections for ambiguous elems (x still live); signed deltas ----
    float s1 = 0.f, s2 = 0.f, s3 = 0.f, s4 = 0.f;
    unsigned int om1 = 0u, om2 = 0u, om3 = 0u, om4 = 0u;
    if (ambm) {
        const unsigned long long T1 = Tk[wrow][0], T2 = Tk[wrow][1],
                                 T3 = Tk[wrow][2], T4 = Tk[wrow][3];
        const float* xv = (const float*)X;
        unsigned int am = ambm;
        while (am) {
            int i = __ffs(am) - 1; am &= am - 1;
            float x = xv[i];
            float y = x + OFFF;
            float e = __expf(x);
            int gidx = 4 * lane + 128 * (i >> 2) + (i & 3);
            unsigned int b = (binw[i >> 2] >> (8 * (i & 3))) & 255u;
            unsigned long long key = ((unsigned long long)b << 48)
                | ((unsigned long long)mono_key(x) << 16)
                | (unsigned long long)(65535u - (unsigned int)gidx);
            // per k: in = exact membership; fp = what pass B will add
            {
                bool fp = y > E1, in = (b == bk1) ? (key >= T1) : fp;
                if (in) om1 |= 1u << i;
                if (in != fp) s1 += in ? e : -e;
            }
            {
                bool fp = y > E2, in = (b == bk2) ? (key >= T2) : fp;
                if (in) om2 |= 1u << i;
                if (in != fp) s2 += in ? e : -e;
            }
            {
                bool fp = y > E3, in = (b == bk3) ? (key >= T3) : fp;
                if (in) om3 |= 1u << i;
                if (in != fp) s3 += in ? e : -e;
            }
            {
                bool fp = y > E4, in = (b == bk4) ? (key >= T4) : fp;
                if (in) om4 |= 1u << i;
                if (in != fp) s4 += in ? e : -e;
            }
        }
    }

    // ---- pass B: exp + fma-pipe predicated sums; X := exp(x) ----
    {
        float* xv = (float*)X;
        #pragma unroll
        for (int i = 0; i < 16; i++) {
            float x = xv[i];
            float y = x + OFFF;
            float e = __expf(x);          // softmax shift-invariant; |x| ~ 5
            xv[i] = e;
            if (y > E1) s1 += e;
            if (y > E2) s2 += e;
            if (y > E3) s3 += e;
            if (y > E4) s4 += e;
        }
        #pragma unroll
        for (int o = 16; o > 0; o >>= 1) {
            s1 += __shfl_xor_sync(0xffffffffu, s1, o);
            s2 += __shfl_xor_sync(0xffffffffu, s2, o);
            s3 += __shfl_xor_sync(0xffffffffu, s3, o);
            s4 += __shfl_xor_sync(0xffffffffu, s4, o);
        }
    }
    const float q1 = __fdividef(w1, s1), q2 = __fdividef(w2, s2),
                q3 = __fdividef(w3, s3), q4 = __fdividef(w4, s4);

    // ---- build coef LUT over bins (valid for all non-amb elements) ----
    #pragma unroll
    for (int j = 0; j < 8; j++) {
        unsigned int b = (unsigned int)(lane * 8 + j);
        float cf = 0.f;
        if (b < bk1) cf += q1;
        if (b < bk2) cf += q2;
        if (b < bk3) cf += q3;
        if (b < bk4) cf += q4;
        lut[wrow][b] = cf;
    }
    __syncwarp();

    // ---- write: coef = LUT[bin]; override bits for boundary elems ----
    {
        const float* ev = (const float*)X;
        float4* op = (float4*)(out + (size_t)row * C);
        #pragma unroll
        for (int g = 0; g < 4; g++) {
            float4 o4;
            float* o = (float*)&o4;
            #pragma unroll
            for (int e = 0; e < 4; e++) {
                int i = 4 * g + e;
                unsigned int b = __byte_perm(binw[g], 0u, 0x7770u | (unsigned)e);
                float cf = lut[wrow][b];
                if ((ambm >> i) & 1u) {
                    cf = 0.f;
                    if ((om1 >> i) & 1u) cf += q1;
                    if ((om2 >> i) & 1u) cf += q2;
                    if ((om3 >> i) & 1u) cf += q3;
                    if ((om4 >> i) & 1u) cf += q4;
                }
                o[e] = ev[i] * cf;
            }
            op[lane + 32 * g] = o4;
        }
    }
}

extern "C" void kernel_launch(void* const* d_in, const int* in_sizes, int n_in,
                              void* d_out, int out_size)
{
    const float* attn = (const float*)d_in[0];
    const float* w1   = (const float*)d_in[1];
    const float* w2   = (const float*)d_in[2];
    const float* w3   = (const float*)d_in[3];
    const float* w4   = (const float*)d_in[4];
    float* out = (float*)d_out;

    int rows   = in_sizes[0] / C;
    int blocks = rows / RPB;
    multiscale_topk_kernel<<<blocks, 32 * RPB>>>(attn, w1, w2, w3, w4, out);
}

// round 9
// speedup vs baseline: 1.3296x; 1.0871x over previous
#include <cuda_runtime.h>
#include <cstdint>

#define C 512
#define NBINS 256
#define RPB 8
#define LIST_CAP 512   // = C: boundary bins can never overflow

// k thresholds for C=512: int(C/2), int(C*2/3), int(C*3/4), int(C*4/5)
#define K1 256u
#define K2 341u
#define K3 384u
#define K4 409u

// Fixed-exponent quantization: y = x + 3*2^17 has ulp = 1/32 over |x|<4.
#define OFFF 393216.0f
#define TOPB 0x48C00080u   // bits(OFFF + 4.0f)

// Monotone 32-bit key: larger float -> larger key. (Boundary elems only.)
__device__ __forceinline__ unsigned int mono_key(float x)
{
    unsigned int u = __float_as_uint(x);
    return u ^ (((unsigned int)((int)u >> 31)) | 0x80000000u);
}

// zero-byte detector: 0x80 set in each byte of t that is zero
#define ZB(t) ((((t) - 0x01010101u) & ~(t)) & 0x80808080u)

__global__ __launch_bounds__(32 * RPB, 4)
void multiscale_topk_kernel(const float* __restrict__ attn,
                            const float* __restrict__ w1p,
                            const float* __restrict__ w2p,
                            const float* __restrict__ w3p,
                            const float* __restrict__ w4p,
                            float* __restrict__ out)
{
    __shared__ unsigned int       cnt[RPB][NBINS];
    __shared__ unsigned long long list[RPB][LIST_CAP];
    __shared__ unsigned int       listN[RPB];
    __shared__ uint4              bbs[RPB];          // per k: (bin<<16) | G
    __shared__ unsigned long long Tk[RPB][4];        // 64-bit threshold keys

    const int lane = threadIdx.x & 31;
    const int wrow = threadIdx.x >> 5;
    const int row  = blockIdx.x * RPB + wrow;
    const float* __restrict__ rp = attn + (size_t)row * C;

    // ---- init ----
    {
        uint4 z = make_uint4(0u, 0u, 0u, 0u);
        *(uint4*)&cnt[wrow][lane * 8]     = z;
        *(uint4*)&cnt[wrow][lane * 8 + 4] = z;
        if (lane == 0) listN[wrow] = 0u;
    }
    const float w1 = __ldg(w1p), w2 = __ldg(w2p), w3 = __ldg(w3p), w4 = __ldg(w4p);

    // ---- load 16 elems / lane (coalesced float4) ----
    float4 X[4];
    #pragma unroll
    for (int g = 0; g < 4; g++)
        X[g] = ((const float4*)rp)[lane + 32 * g];

    __syncwarp();

    // ---- pass A: exact-bit bins + count histogram (x stays in X) ----
    unsigned int binw[4];
    {
        const float* xv = (const float*)X;
        #pragma unroll
        for (int g = 0; g < 4; g++) {
            unsigned int bw = 0u;
            #pragma unroll
            for (int e = 0; e < 4; e++) {
                float y = xv[4 * g + e] + OFFF;
                int raw = (int)TOPB - (int)__float_as_uint(y);
                int b = max(0, min(255, raw));
                bw = __byte_perm(bw, (unsigned int)b, 0x3210u + 0x1000u * (unsigned)e
                                 - 0x0111u * ((0x3210u >> (4 * e)) & 0xFu) * 0u);
                bw = (e == 0) ? (unsigned int)b
                              : (bw & ~(255u << (8 * e))) | ((unsigned int)b << (8 * e));
                atomicAdd(&cnt[wrow][b], 1u);
            }
            binw[g] = bw;
        }
    }
    __syncwarp();

    // ---- scan 256 bins; locate the 4 boundary bins (G < k <= G+cnt) ----
    {
        uint4 c0 = *(uint4*)&cnt[wrow][lane * 8];
        uint4 c1 = *(uint4*)&cnt[wrow][lane * 8 + 4];
        unsigned int cc[8] = {c0.x, c0.y, c0.z, c0.w, c1.x, c1.y, c1.z, c1.w};
        unsigned int tot = 0u;
        #pragma unroll
        for (int j = 0; j < 8; j++) tot += cc[j];
        unsigned int ti = tot;
        #pragma unroll
        for (int d = 1; d < 32; d <<= 1) {
            unsigned int v = __shfl_up_sync(0xffffffffu, ti, d);
            if (lane >= d) ti += v;
        }
        unsigned int run = ti - tot;               // exclusive prefix
        #pragma unroll
        for (int j = 0; j < 8; j++) {
            unsigned int G = run, E = run + cc[j];
            if (G < K4 && E >= K1) {
                unsigned int w = ((unsigned int)(lane * 8 + j) << 16) | G;
                if (G < K1 && E >= K1) bbs[wrow].x = w;
                if (G < K2 && E >= K2) bbs[wrow].y = w;
                if (G < K3 && E >= K3) bbs[wrow].z = w;
                if (G < K4 && E >= K4) bbs[wrow].w = w;
            }
            run = E;
        }
    }
    __syncwarp();

    const uint4 B = bbs[wrow];
    const unsigned int bk1 = B.x >> 16, bk2 = B.y >> 16, bk3 = B.z >> 16, bk4 = B.w >> 16;
    const unsigned int gg1 = B.x & 0xFFFFu, gg2 = B.y & 0xFFFFu,
                       gg3 = B.z & 0xFFFFu, gg4 = B.w & 0xFFFFu;
    // Exact fast-path edges: raw < b_k  <=>  y > E_k  (both positive floats)
    const float E1 = __uint_as_float(TOPB - bk1);
    const float E2 = __uint_as_float(TOPB - bk2);
    const float E3 = __uint_as_float(TOPB - bk3);
    const float E4 = __uint_as_float(TOPB - bk4);

    // ---- vectorized amb detection (bin byte == some boundary bin) ----
    unsigned int ambm = 0u;
    {
        const unsigned int k1x4 = bk1 * 0x01010101u;
        const unsigned int k2x4 = bk2 * 0x01010101u;
        const unsigned int k3x4 = bk3 * 0x01010101u;
        const unsigned int k4x4 = bk4 * 0x01010101u;
        #pragma unroll
        for (int g = 0; g < 4; g++) {
            unsigned int w = binw[g];
            unsigned int z = ZB(w ^ k1x4) | ZB(w ^ k2x4) | ZB(w ^ k3x4) | ZB(w ^ k4x4);
            ambm |= ((((z >> 7) * 0x01020408u) >> 24) & 0xFu) << (4 * g);
        }
    }

    // ---- gather boundary candidates (x still live in X) ----
    {
        const float* xv = (const float*)X;
        unsigned int am = ambm;
        while (am) {
            int i = __ffs(am) - 1; am &= am - 1;
            int gidx = 4 * lane + 128 * (i >> 2) + (i & 3);
            unsigned int b = (binw[i >> 2] >> (8 * (i & 3))) & 255u;
            unsigned long long key = ((unsigned long long)b << 48)
                | ((unsigned long long)mono_key(xv[i]) << 16)
                | (unsigned long long)(65535u - (unsigned int)gidx);
            unsigned int pos = atomicAdd(&listN[wrow], 1u);
            list[wrow][pos] = key;
        }
    }
    __syncwarp();

    // ---- selection: exact k-th largest key per boundary bin ----
    {
        const unsigned int M = listN[wrow];
        for (unsigned int j = lane; j < M; j += 32) {
            unsigned long long cj = list[wrow][j];
            unsigned int hb = (unsigned int)(cj >> 48);
            unsigned int g0 = (hb == bk1) ? gg1 : (hb == bk2) ? gg2
                            : (hb == bk3) ? gg3 : gg4;
            unsigned int r = g0;
            for (unsigned int q = 0u; q < M; q++) {
                unsigned long long cq = list[wrow][q];
                r += (unsigned int)((cq > cj) && ((unsigned int)(cq >> 48) == hb));
            }
            if (hb == bk1 && r == K1 - 1u) Tk[wrow][0] = cj;
            if (hb == bk2 && r == K2 - 1u) Tk[wrow][1] = cj;
            if (hb == bk3 && r == K3 - 1u) Tk[wrow][2] = cj;
            if (hb == bk4 && r == K4 - 1u) Tk[wrow][3] = cj;
        }
    }
    __syncwarp();

    // ---- corrections for ambiguous elems (x still live): signed sum deltas
    //      + mask-flip words applied after the fused pass ----
    float s1 = 0.f, s2 = 0.f, s3 = 0.f, s4 = 0.f;
    unsigned int f1 = 0u, f2 = 0u, f3 = 0u, f4 = 0u;
    if (ambm) {
        const unsigned long long T1 = Tk[wrow][0], T2 = Tk[wrow][1],
                                 T3 = Tk[wrow][2], T4 = Tk[wrow][3];
        const float* xv = (const float*)X;
        unsigned int am = ambm;
        while (am) {
            int i = __ffs(am) - 1; am &= am - 1;
            float x = xv[i];
            float y = x + OFFF;
            float e = __expf(x);
            int gidx = 4 * lane + 128 * (i >> 2) + (i & 3);
            unsigned int b = (binw[i >> 2] >> (8 * (i & 3))) & 255u;
            unsigned long long key = ((unsigned long long)b << 48)
                | ((unsigned long long)mono_key(x) << 16)
                | (unsigned long long)(65535u - (unsigned int)gidx);
            {
                bool fp = y > E1, in = (b == bk1) ? (key >= T1) : fp;
                if (in != fp) { f1 |= 1u << i; s1 += in ? e : -e; }
            }
            {
                bool fp = y > E2, in = (b == bk2) ? (key >= T2) : fp;
                if (in != fp) { f2 |= 1u << i; s2 += in ? e : -e; }
            }
            {
                bool fp = y > E3, in = (b == bk3) ? (key >= T3) : fp;
                if (in != fp) { f3 |= 1u << i; s3 += in ? e : -e; }
            }
            {
                bool fp = y > E4, in = (b == bk4) ? (key >= T4) : fp;
                if (in != fp) { f4 |= 1u << i; s4 += in ? e : -e; }
            }
        }
    }

    // ---- fused pass: exp + fma-pipe membership + sums + masks; X := exp(x) ----
    unsigned int m1 = 0u, m2 = 0u, m3 = 0u, m4 = 0u;
    {
        float* xv = (float*)X;
        #pragma unroll
        for (int i = 0; i < 16; i++) {
            float x = xv[i];
            float y = x + OFFF;
            float e = __expf(x);          // softmax shift-invariant; |x| ~ 5
            xv[i] = e;
            if (y > E1) { s1 += e; m1 |= 1u << i; }
            if (y > E2) { s2 += e; m2 |= 1u << i; }
            if (y > E3) { s3 += e; m3 |= 1u << i; }
            if (y > E4) { s4 += e; m4 |= 1u << i; }
        }
    }
    m1 ^= f1; m2 ^= f2; m3 ^= f3; m4 ^= f4;

    #pragma unroll
    for (int o = 16; o > 0; o >>= 1) {
        s1 += __shfl_xor_sync(0xffffffffu, s1, o);
        s2 += __shfl_xor_sync(0xffffffffu, s2, o);
        s3 += __shfl_xor_sync(0xffffffffu, s3, o);
        s4 += __shfl_xor_sync(0xffffffffu, s4, o);
    }
    const float q1 = __fdividef(w1, s1), q2 = __fdividef(w2, s2),
                q3 = __fdividef(w3, s3), q4 = __fdividef(w4, s4);

    // ---- write from masks ----
    {
        const float* ev = (const float*)X;
        float4* op = (float4*)(out + (size_t)row * C);
        #pragma unroll
        for (int g = 0; g < 4; g++) {
            float4 o4;
            float* o = (float*)&o4;
            #pragma unroll
            for (int e = 0; e < 4; e++) {
                int i = 4 * g + e;
                float coef = 0.f;
                if ((m1 >> i) & 1u) coef += q1;
                if ((m2 >> i) & 1u) coef += q2;
                if ((m3 >> i) & 1u) coef += q3;
                if ((m4 >> i) & 1u) coef += q4;
                o[e] = ev[i] * coef;
            }
            op[lane + 32 * g] = o4;
        }
    }
}

extern "C" void kernel_launch(void* const* d_in, const int* in_sizes, int n_in,
                              void* d_out, int out_size)
{
    const float* attn = (const float*)d_in[0];
    const float* w1   = (const float*)d_in[1];
    const float* w2   = (const float*)d_in[2];
    const float* w3   = (const float*)d_in[3];
    const float* w4   = (const float*)d_in[4];
    float* out = (float*)d_out;

    int rows   = in_sizes[0] / C;
    int blocks = rows / RPB;
    multiscale_topk_kernel<<<blocks, 32 * RPB>>>(attn, w1, w2, w3, w4, out);
}